// round 10
// baseline (speedup 1.0000x reference)
#include <cuda_runtime.h>
#include <cstdint>

// Problem: out[N=100000,128] = zeros; out[i1]+=deltas[:,:128]; out[i2]+=deltas[:,128:256];
//          b = deltas[:,256:320].  d_out layout: [ out : N*128 fp32 ][ b : E*64 fp32 ]
//
// R9: split each edge's reduction across two hardware pipes:
//   ux (512B) -> SMEM -> cp.reduce.async.bulk (TMA engine)   [R3 path]
//   uy (512B) -> registers -> red.global.add.v4 (LSU/LTS)    [R2 path]
// R2 showed pure-REDG is LSU-capped (~155us); R3 showed pure-TMA serializes on
// lane0 chains (~146us). Halving each pipe's load puts both under the ~137us
// DRAM floor. SMEM halves to 8KB/block; uy path has zero sync overhead.

#define WARPS_PER_BLOCK 8
#define THREADS_PER_BLOCK (WARPS_PER_BLOCK * 32)
#define GRID_BLOCKS 2048

__device__ __forceinline__ uint64_t make_evict_last_policy() {
    uint64_t pol;
    asm("createpolicy.fractional.L2::evict_last.b64 %0, 1.0;" : "=l"(pol));
    return pol;
}

__device__ __forceinline__ uint64_t make_evict_first_policy() {
    uint64_t pol;
    asm("createpolicy.fractional.L2::evict_first.b64 %0, 1.0;" : "=l"(pol));
    return pol;
}

__global__ void zero_out_kernel(float4* __restrict__ out4, long n4) {
    long i = blockIdx.x * (long)blockDim.x + threadIdx.x;
    if (i < n4) {
        uint64_t pol = make_evict_last_policy();
        asm volatile("st.global.L2::cache_hint.v4.f32 [%0], {%1,%2,%3,%4}, %5;"
                     :: "l"(out4 + i), "f"(0.f), "f"(0.f), "f"(0.f), "f"(0.f), "l"(pol)
                     : "memory");
    }
}

__device__ __forceinline__ float4 ldg_stream(const float4* p, uint64_t pol) {
    float4 v;
    asm("ld.global.nc.L2::cache_hint.v4.f32 {%0,%1,%2,%3}, [%4], %5;"
        : "=f"(v.x), "=f"(v.y), "=f"(v.z), "=f"(v.w) : "l"(p), "l"(pol));
    return v;
}

__device__ __forceinline__ void stg_stream(float4* p, float4 v) {
    asm volatile("st.global.cs.v4.f32 [%0], {%1,%2,%3,%4};"
                 :: "l"(p), "f"(v.x), "f"(v.y), "f"(v.z), "f"(v.w)
                 : "memory");
}

__device__ __forceinline__ void red_add_v4_el(float* p, float4 v, uint64_t pol) {
    asm volatile("red.global.add.L2::cache_hint.v4.f32 [%0], {%1,%2,%3,%4}, %5;"
                 :: "l"(p), "f"(v.x), "f"(v.y), "f"(v.z), "f"(v.w), "l"(pol)
                 : "memory");
}

__device__ __forceinline__ void bulk_reduce_add_f32(float* gdst, uint32_t ssrc,
                                                    uint32_t bytes, uint64_t pol) {
    asm volatile(
        "cp.reduce.async.bulk.global.shared::cta.bulk_group.L2::cache_hint.add.f32 "
        "[%0], [%1], %2, %3;"
        :: "l"(gdst), "r"(ssrc), "r"(bytes), "l"(pol)
        : "memory");
}

__global__ void __launch_bounds__(THREADS_PER_BLOCK, 8)
scatter_kernel(const float4* __restrict__ deltas4,  // E * 80 float4
               const int*    __restrict__ i1,       // E
               const int*    __restrict__ i2,       // E
               float*        __restrict__ out,      // N * 128 fp32
               float4*       __restrict__ bout4,    // E * 16 float4
               long E, long nwarps)
{
    // Per-warp double buffer for ux only: 2 x 32 float4 = 1 KB/warp, 8 KB/block.
    __shared__ __align__(16) float4 buf[WARPS_PER_BLOCK][2][32];

    const int wid  = threadIdx.x >> 5;
    const int lane = threadIdx.x & 31;
    const long gw  = (long)blockIdx.x * WARPS_PER_BLOCK + wid;

    const uint64_t pol_ef = make_evict_first_policy();
    const uint64_t pol_el = make_evict_last_policy();

    int parity = 0;
    for (long e = gw; e < E; e += nwarps, parity ^= 1) {
        // Reclaim this parity's ux buffer (handed to TMA 2 iterations ago).
        if (lane == 0)
            asm volatile("cp.async.bulk.wait_group.read 1;" ::: "memory");
        __syncwarp();

        const float4* row = deltas4 + e * 80;

        // Issue all three loads back-to-back (independent streams).
        float4 v0 = ldg_stream(row + lane,      pol_ef);   // ux chunk
        float4 v1 = ldg_stream(row + 32 + lane, pol_ef);   // uy chunk
        float4 vb;
        if (lane < 16) vb = ldg_stream(row + 64 + lane, pol_ef);  // b chunk

        // ux -> SMEM (TMA pipe)
        buf[wid][parity][lane] = v0;

        // uy -> direct red.v4 (LSU/LTS pipe), one 16B chunk per lane.
        int r2 = __ldg(&i2[e]);
        red_add_v4_el(out + (long)r2 * 128 + lane * 4, v1, pol_el);

        // b -> straight to output.
        if (lane < 16) stg_stream(bout4 + e * 16 + lane, vb);

        __syncwarp();
        if (lane == 0) {
            asm volatile("fence.proxy.async.shared::cta;" ::: "memory");
            int r1 = __ldg(&i1[e]);
            uint32_t s = (uint32_t)__cvta_generic_to_shared(&buf[wid][parity][0]);
            bulk_reduce_add_f32(out + (long)r1 * 128, s, 512, pol_el);
            asm volatile("cp.async.bulk.commit_group;" ::: "memory");
        }
    }

    // Drain all pending bulk groups before exit.
    if (lane == 0)
        asm volatile("cp.async.bulk.wait_group 0;" ::: "memory");
}

extern "C" void kernel_launch(void* const* d_in, const int* in_sizes, int n_in,
                              void* d_out, int out_size)
{
    // metadata order: unary(N*128 f32), binary(E*64 f32), deltas(E*320 f32),
    //                 index1(E i32), index2(E i32)
    const long N = in_sizes[0] / 128;
    const long E = in_sizes[2] / 320;

    const float4* deltas4 = (const float4*)d_in[2];
    const int*    i1      = (const int*)d_in[3];
    const int*    i2      = (const int*)d_in[4];

    float*  out   = (float*)d_out;                       // N*128
    float4* bout4 = (float4*)((float*)d_out + N * 128);  // E*16 float4

    // 1) zero the scatter target and pin it in L2 (evict_last)
    {
        long n4 = (N * 128) / 4;
        int  threads = 256;
        long blocks = (n4 + threads - 1) / threads;
        zero_out_kernel<<<(unsigned)blocks, threads>>>((float4*)out, n4);
    }

    // 2) scatter-add (TMA pipe for ux, REDG pipe for uy) + b copy
    {
        long nwarps = (long)GRID_BLOCKS * WARPS_PER_BLOCK;
        scatter_kernel<<<GRID_BLOCKS, THREADS_PER_BLOCK>>>(deltas4, i1, i2, out, bout4, E, nwarps);
    }
}

// round 11
// speedup vs baseline: 1.0525x; 1.0525x over previous
#include <cuda_runtime.h>
#include <cstdint>

// Problem: out[N=100000,128] = zeros; out[i1]+=deltas[:,:128]; out[i2]+=deltas[:,128:256];
//          b = deltas[:,256:320].  d_out layout: [ out : N*128 fp32 ][ b : E*64 fp32 ]
//
// R10 = R3 (best: 145.7us scatter) with all delta loads widened to 256-bit
// (ld.global.nc.L2::evict_first.v8.b32 — the width this ptxas requires for the
// compact evict_first hint). ux||uy = 1024B = exactly 1 LDG.256/lane (was 2
// LDG.128); b = 256B = 1 LDG.256 on 8 lanes (was 16 lanes of LDG.128). Halves
// LSU issue slots + scoreboard waits per iteration. TMA reduce path unchanged.

#define WARPS_PER_BLOCK 8
#define THREADS_PER_BLOCK (WARPS_PER_BLOCK * 32)
#define GRID_BLOCKS 2048

__device__ __forceinline__ uint64_t make_evict_last_policy() {
    uint64_t pol;
    asm("createpolicy.fractional.L2::evict_last.b64 %0, 1.0;" : "=l"(pol));
    return pol;
}

__global__ void zero_out_kernel(float4* __restrict__ out4, long n4) {
    long i = blockIdx.x * (long)blockDim.x + threadIdx.x;
    if (i < n4) {
        uint64_t pol = make_evict_last_policy();
        asm volatile("st.global.L2::cache_hint.v4.f32 [%0], {%1,%2,%3,%4}, %5;"
                     :: "l"(out4 + i), "f"(0.f), "f"(0.f), "f"(0.f), "f"(0.f), "l"(pol)
                     : "memory");
    }
}

struct V8 { uint32_t r[8]; };

__device__ __forceinline__ V8 ldg256_stream(const void* p) {
    V8 v;
    asm("ld.global.nc.L2::evict_first.v8.b32 {%0,%1,%2,%3,%4,%5,%6,%7}, [%8];"
        : "=r"(v.r[0]), "=r"(v.r[1]), "=r"(v.r[2]), "=r"(v.r[3]),
          "=r"(v.r[4]), "=r"(v.r[5]), "=r"(v.r[6]), "=r"(v.r[7])
        : "l"(p));
    return v;
}

__device__ __forceinline__ void sts128x2(uint32_t sdst, const V8& v) {
    asm volatile("st.shared.v4.b32 [%0], {%1,%2,%3,%4};"
                 :: "r"(sdst), "r"(v.r[0]), "r"(v.r[1]), "r"(v.r[2]), "r"(v.r[3])
                 : "memory");
    asm volatile("st.shared.v4.b32 [%0], {%1,%2,%3,%4};"
                 :: "r"(sdst + 16), "r"(v.r[4]), "r"(v.r[5]), "r"(v.r[6]), "r"(v.r[7])
                 : "memory");
}

__device__ __forceinline__ void stg_stream_v4(void* p, const uint32_t* r) {
    asm volatile("st.global.cs.v4.b32 [%0], {%1,%2,%3,%4};"
                 :: "l"(p), "r"(r[0]), "r"(r[1]), "r"(r[2]), "r"(r[3])
                 : "memory");
}

__device__ __forceinline__ void bulk_reduce_add_f32(float* gdst, uint32_t ssrc,
                                                    uint32_t bytes, uint64_t pol) {
    asm volatile(
        "cp.reduce.async.bulk.global.shared::cta.bulk_group.L2::cache_hint.add.f32 "
        "[%0], [%1], %2, %3;"
        :: "l"(gdst), "r"(ssrc), "r"(bytes), "l"(pol)
        : "memory");
}

__global__ void __launch_bounds__(THREADS_PER_BLOCK, 8)
scatter_kernel(const float* __restrict__ deltas,   // E * 320 fp32
               const int*   __restrict__ i1,       // E
               const int*   __restrict__ i2,       // E
               float*       __restrict__ out,      // N * 128 fp32
               float*       __restrict__ bout,     // E * 64 fp32
               long E, long nwarps)
{
    // Per-warp double buffer: 2 x 1024 B (ux 512 || uy 512) = 16 KB/block.
    __shared__ __align__(32) float4 buf[WARPS_PER_BLOCK][2][64];

    const int wid  = threadIdx.x >> 5;
    const int lane = threadIdx.x & 31;
    const long gw  = (long)blockIdx.x * WARPS_PER_BLOCK + wid;

    const uint64_t pol_el = make_evict_last_policy();
    const uint32_t sbase  = (uint32_t)__cvta_generic_to_shared(&buf[wid][0][0]);

    int parity = 0;
    for (long e = gw; e < E; e += nwarps, parity ^= 1) {
        // Reclaim this parity's buffer (handed to TMA 2 iterations ago).
        if (lane == 0)
            asm volatile("cp.async.bulk.wait_group.read 1;" ::: "memory");
        __syncwarp();

        const float* row = deltas + e * 320;

        // ux||uy (1024B): one 32B load per lane, coalesced.
        V8 v = ldg256_stream(row + lane * 8);
        sts128x2(sbase + parity * 1024 + lane * 32, v);

        // b (256B): one 32B load on 8 lanes, straight to output.
        if (lane < 8) {
            V8 vb = ldg256_stream(row + 256 + lane * 8);
            float* bp = bout + e * 64 + lane * 8;
            stg_stream_v4(bp,     vb.r);
            stg_stream_v4(bp + 4, vb.r + 4);
        }
        __syncwarp();

        if (lane == 0) {
            asm volatile("fence.proxy.async.shared::cta;" ::: "memory");
            int r1 = __ldg(&i1[e]);
            int r2 = __ldg(&i2[e]);
            uint32_t s = sbase + parity * 1024;
            bulk_reduce_add_f32(out + (long)r1 * 128, s,       512, pol_el);
            bulk_reduce_add_f32(out + (long)r2 * 128, s + 512, 512, pol_el);
            asm volatile("cp.async.bulk.commit_group;" ::: "memory");
        }
    }

    // Drain all pending bulk groups before exit.
    if (lane == 0)
        asm volatile("cp.async.bulk.wait_group 0;" ::: "memory");
}

extern "C" void kernel_launch(void* const* d_in, const int* in_sizes, int n_in,
                              void* d_out, int out_size)
{
    // metadata order: unary(N*128 f32), binary(E*64 f32), deltas(E*320 f32),
    //                 index1(E i32), index2(E i32)
    const long N = in_sizes[0] / 128;
    const long E = in_sizes[2] / 320;

    const float* deltas = (const float*)d_in[2];
    const int*   i1     = (const int*)d_in[3];
    const int*   i2     = (const int*)d_in[4];

    float* out  = (float*)d_out;            // N*128
    float* bout = (float*)d_out + N * 128;  // E*64

    // 1) zero the scatter target and pin it in L2 (evict_last)
    {
        long n4 = (N * 128) / 4;
        int  threads = 256;
        long blocks = (n4 + threads - 1) / threads;
        zero_out_kernel<<<(unsigned)blocks, threads>>>((float4*)out, n4);
    }

    // 2) scatter-add (TMA bulk-reduce, 256-bit loads) + b copy
    {
        long nwarps = (long)GRID_BLOCKS * WARPS_PER_BLOCK;
        scatter_kernel<<<GRID_BLOCKS, THREADS_PER_BLOCK>>>(deltas, i1, i2, out, bout, E, nwarps);
    }
}